// round 14
// baseline (speedup 1.0000x reference)
#include <cuda_runtime.h>
#include <cstdint>

#define N_NODES 100000
#define N_EDGES 1600000
#define CH 64
#define EDIM 16
#define HID 32
#define NB_SCAN ((N_NODES + 1023) / 1024)   // 98

// Scratch (static device globals — allocation-free)
__device__ float g_xw[N_NODES * CH];              // x @ W
__device__ float g_alpha[N_EDGES];                // edge gate
__device__ int   g_tick[N_EDGES];                 // within-col ticket (from edge)
__device__ float g_deg[N_NODES];                  // degree -> dis
__device__ int   g_cnt[N_NODES];
__device__ int   g_rowptr[N_NODES];
__device__ unsigned long long g_epack[N_EDGES];   // (norm<<32 | row) per CSR slot
__device__ int   g_is64;
__device__ int   g_base;                          // ticket counter for block offsets

// ---------------------------------------------------------------------------
// dtype detection (one warp, parallel) + zero deg/cnt + zero ticket
// ---------------------------------------------------------------------------
__global__ void k_detect_init(const long long* __restrict__ ei64) {
    int i = blockIdx.x * blockDim.x + threadIdx.x;
    if (blockIdx.x == 0 && threadIdx.x < 32) {
        long long v0 = ei64[threadIdx.x];
        long long v1 = ei64[threadIdx.x + 32];
        int ok = (v0 >= 0 && v0 < N_NODES && v1 >= 0 && v1 < N_NODES) ? 1 : 0;
        unsigned m = __ballot_sync(0xffffffffu, ok);
        if (threadIdx.x == 0) { g_is64 = (m == 0xffffffffu); g_base = 0; }
    }
    if (i < N_NODES) { g_deg[i] = 0.0f; g_cnt[i] = 0; }
}

// ---------------------------------------------------------------------------
// 1) xw = x @ W — smem-tiled GEMM.  64 nodes/block, 4x4 register tile/thread.
// ---------------------------------------------------------------------------
__global__ void k_xw(const float* __restrict__ x, const float* __restrict__ W) {
    __shared__ float Ws[CH * CH];        // [k][c]  16KB
    __shared__ float xs[CH][CH];         // [k][n]  16KB (transposed tile)

    const int tid = threadIdx.x;
    const int nodeBase = blockIdx.x * 64;

    for (int i = tid; i < CH * CH / 4; i += 256)
        ((float4*)Ws)[i] = ((const float4*)W)[i];

    {
        int n  = tid >> 2;               // 0..63
        int k4 = (tid & 3) * 4;          // 0,4,8,12 (+16 per iter)
        int gn = nodeBase + n;
        #pragma unroll
        for (int it = 0; it < 4; ++it) {
            int k = k4 + it * 16;
            float4 v = make_float4(0.f, 0.f, 0.f, 0.f);
            if (gn < N_NODES) v = *(const float4*)(x + (size_t)gn * CH + k);
            xs[k + 0][n] = v.x; xs[k + 1][n] = v.y;
            xs[k + 2][n] = v.z; xs[k + 3][n] = v.w;
        }
    }
    __syncthreads();

    const int c0 = (tid & 15) * 4;
    const int n0 = (tid >> 4) * 4;
    float acc[4][4];
    #pragma unroll
    for (int i = 0; i < 4; ++i)
        #pragma unroll
        for (int j = 0; j < 4; ++j) acc[i][j] = 0.f;

    #pragma unroll 4
    for (int k = 0; k < CH; ++k) {
        float4 a = *(const float4*)&xs[k][n0];
        float4 w = *(const float4*)&Ws[k * CH + c0];
        acc[0][0] = fmaf(a.x, w.x, acc[0][0]); acc[0][1] = fmaf(a.x, w.y, acc[0][1]);
        acc[0][2] = fmaf(a.x, w.z, acc[0][2]); acc[0][3] = fmaf(a.x, w.w, acc[0][3]);
        acc[1][0] = fmaf(a.y, w.x, acc[1][0]); acc[1][1] = fmaf(a.y, w.y, acc[1][1]);
        acc[1][2] = fmaf(a.y, w.z, acc[1][2]); acc[1][3] = fmaf(a.y, w.w, acc[1][3]);
        acc[2][0] = fmaf(a.z, w.x, acc[2][0]); acc[2][1] = fmaf(a.z, w.y, acc[2][1]);
        acc[2][2] = fmaf(a.z, w.z, acc[2][2]); acc[2][3] = fmaf(a.z, w.w, acc[2][3]);
        acc[3][0] = fmaf(a.w, w.x, acc[3][0]); acc[3][1] = fmaf(a.w, w.y, acc[3][1]);
        acc[3][2] = fmaf(a.w, w.z, acc[3][2]); acc[3][3] = fmaf(a.w, w.w, acc[3][3]);
    }

    #pragma unroll
    for (int i = 0; i < 4; ++i) {
        int gn = nodeBase + n0 + i;
        if (gn < N_NODES)
            *(float4*)(g_xw + (size_t)gn * CH + c0) =
                make_float4(acc[i][0], acc[i][1], acc[i][2], acc[i][3]);
    }
}

// ---------------------------------------------------------------------------
// 2) edge MLP gate + degree + count-with-ticket.  2 edges/thread.
//    The cnt atomic's RETURN VALUE is the edge's within-column slot.
// ---------------------------------------------------------------------------
__global__ void k_edge(const float* __restrict__ ea,
                       const void* __restrict__ ei,
                       const float* __restrict__ W1, const float* __restrict__ b1,
                       const float* __restrict__ W2, const float* __restrict__ b2) {
    __shared__ __align__(16) float sW1t[HID * EDIM];   // [j][k] transposed
    __shared__ float sb1[HID];
    __shared__ float sW2[HID];
    __shared__ float sb2;
    for (int i = threadIdx.x; i < HID * EDIM; i += blockDim.x) {
        int j = i >> 4, k = i & 15;
        sW1t[i] = W1[k * HID + j];
    }
    if (threadIdx.x < HID) { sb1[threadIdx.x] = b1[threadIdx.x]; sW2[threadIdx.x] = W2[threadIdx.x]; }
    if (threadIdx.x == 0) sb2 = b2[0];
    __syncthreads();

    int t  = blockIdx.x * blockDim.x + threadIdx.x;
    int e0 = 2 * t;
    if (e0 >= N_EDGES) return;      // N_EDGES even -> e0+1 also valid

    float4 A0[4], A1[4];
    {
        const float4* p0 = (const float4*)(ea + (size_t)e0 * EDIM);
        const float4* p1 = (const float4*)(ea + (size_t)(e0 + 1) * EDIM);
        #pragma unroll
        for (int i = 0; i < 4; ++i) { A0[i] = p0[i]; A1[i] = p1[i]; }
    }

    const float4* Wt = (const float4*)sW1t;
    float acc0 = sb2, acc1 = sb2;
    #pragma unroll
    for (int j = 0; j < HID; ++j) {
        float bj = sb1[j];
        float h0 = bj, h1 = bj;
        #pragma unroll
        for (int q = 0; q < 4; ++q) {
            float4 w = Wt[j * 4 + q];
            float4 a = A0[q], c = A1[q];
            h0 = fmaf(a.x, w.x, h0);  h1 = fmaf(c.x, w.x, h1);
            h0 = fmaf(a.y, w.y, h0);  h1 = fmaf(c.y, w.y, h1);
            h0 = fmaf(a.z, w.z, h0);  h1 = fmaf(c.z, w.z, h1);
            h0 = fmaf(a.w, w.w, h0);  h1 = fmaf(c.w, w.w, h1);
        }
        float w2 = sW2[j];
        float s0 = __fdividef(h0, 1.0f + __expf(-h0));   // silu
        float s1 = __fdividef(h1, 1.0f + __expf(-h1));
        acc0 = fmaf(s0, w2, acc0);
        acc1 = fmaf(s1, w2, acc1);
    }
    float alpha0 = __fdividef(1.0f, 1.0f + __expf(-acc0)); // sigmoid
    float alpha1 = __fdividef(1.0f, 1.0f + __expf(-acc1));
    ((float2*)g_alpha)[t] = make_float2(alpha0, alpha1);

    int col0, col1;
    if (g_is64) {
        col0 = (int)((const long long*)ei)[(size_t)N_EDGES + e0];
        col1 = (int)((const long long*)ei)[(size_t)N_EDGES + e0 + 1];
    } else {
        col0 = ((const int*)ei)[(size_t)N_EDGES + e0];
        col1 = ((const int*)ei)[(size_t)N_EDGES + e0 + 1];
    }
    atomicAdd(&g_deg[col0], alpha0);
    atomicAdd(&g_deg[col1], alpha1);
    int tick0 = atomicAdd(&g_cnt[col0], 1);      // ticket = within-col slot
    int tick1 = atomicAdd(&g_cnt[col1], 1);
    ((int2*)g_tick)[t] = make_int2(tick0, tick1);
}

// ---------------------------------------------------------------------------
// 3) single-pass scan: block-local inclusive scan + atomic ticket offsets,
//    rowptr + dis = rsqrt(deg) inline.
// ---------------------------------------------------------------------------
__global__ void k_scan() {
    int i = blockIdx.x * 1024 + threadIdx.x;
    int v = (i < N_NODES) ? g_cnt[i] : 0;
    int lane = threadIdx.x & 31, wid = threadIdx.x >> 5;
    int s = v;
    #pragma unroll
    for (int o = 1; o < 32; o <<= 1) {
        int t = __shfl_up_sync(0xffffffffu, s, o);
        if (lane >= o) s += t;
    }
    __shared__ int wsum[32];
    __shared__ int blkoff;
    if (lane == 31) wsum[wid] = s;
    __syncthreads();
    if (wid == 0) {
        int t = wsum[lane];
        #pragma unroll
        for (int o = 1; o < 32; o <<= 1) {
            int u = __shfl_up_sync(0xffffffffu, t, o);
            if (lane >= o) t += u;
        }
        wsum[lane] = t;
        if (lane == 31) blkoff = atomicAdd(&g_base, t);  // t = block total
    }
    __syncthreads();
    if (i < N_NODES) {
        int incl = s + (wid > 0 ? wsum[wid - 1] : 0);
        g_rowptr[i] = incl - v + blkoff;
        float d = g_deg[i];
        g_deg[i] = (d > 0.0f) ? rsqrtf(d) : 0.0f;
    }
}

// ---------------------------------------------------------------------------
// 4) placement — ATOMIC-FREE: pos = rowptr[col] + tick[e].  2 edges/thread.
// ---------------------------------------------------------------------------
__global__ void k_place(const void* __restrict__ ei) {
    int t = blockIdx.x * blockDim.x + threadIdx.x;
    int e0 = 2 * t;
    if (e0 >= N_EDGES) return;

    int row0, col0, row1, col1;
    if (g_is64) {
        const long long* p = (const long long*)ei;
        row0 = (int)p[e0];     row1 = (int)p[e0 + 1];
        col0 = (int)p[(size_t)N_EDGES + e0];
        col1 = (int)p[(size_t)N_EDGES + e0 + 1];
    } else {
        const int* p = (const int*)ei;
        int2 r = *(const int2*)(p + e0);
        int2 c = *(const int2*)(p + (size_t)N_EDGES + e0);
        row0 = r.x; row1 = r.y; col0 = c.x; col1 = c.y;
    }

    float2 al = ((const float2*)g_alpha)[t];
    int2   tk = ((const int2*)g_tick)[t];

    float n0 = g_deg[row0] * al.x * g_deg[col0];
    float n1 = g_deg[row1] * al.y * g_deg[col1];
    int pos0 = g_rowptr[col0] + tk.x;
    int pos1 = g_rowptr[col1] + tk.y;

    g_epack[pos0] = (unsigned)row0 | ((unsigned long long)__float_as_uint(n0) << 32);
    g_epack[pos1] = (unsigned)row1 | ((unsigned long long)__float_as_uint(n1) << 32);
}

// ---------------------------------------------------------------------------
// 5) gather + bias + LayerNorm + SiLU + residual.  One warp per node, MLP=8.
// ---------------------------------------------------------------------------
__global__ void k_gather_ln(const float* __restrict__ x, const float* __restrict__ b,
                            const float* __restrict__ gamma, const float* __restrict__ beta,
                            float* __restrict__ out) {
    __shared__ unsigned long long stage[8][40];
    int wip  = threadIdx.x >> 5;
    int lane = threadIdx.x & 31;
    int node = (blockIdx.x * blockDim.x + threadIdx.x) >> 5;
    if (node >= N_NODES) return;

    if (lane < 8) stage[wip][32 + lane] = 0ull;

    int start = g_rowptr[node];
    int cnt   = g_cnt[node];

    float ax[8], ay[8];
    #pragma unroll
    for (int i = 0; i < 8; ++i) { ax[i] = 0.f; ay[i] = 0.f; }

    for (int base = 0; base < cnt; base += 32) {
        int m = cnt - base; if (m > 32) m = 32;
        unsigned long long p = 0ull;
        if (lane < m) p = g_epack[start + base + lane];
        stage[wip][lane] = p;
        __syncwarp();
        int m8 = (m + 7) & ~7;
        #pragma unroll 1
        for (int j = 0; j < m8; j += 8) {
            int   r[8]; float w[8];
            #pragma unroll
            for (int q = 0; q < 8; ++q) {
                unsigned long long pq = stage[wip][j + q];
                r[q] = (int)(unsigned)pq;
                w[q] = __uint_as_float((unsigned)(pq >> 32));
            }
            float2 v[8];
            #pragma unroll
            for (int q = 0; q < 8; ++q)
                v[q] = ((const float2*)(g_xw + (size_t)r[q] * CH))[lane];
            #pragma unroll
            for (int q = 0; q < 8; ++q) {
                ax[q] = fmaf(v[q].x, w[q], ax[q]);
                ay[q] = fmaf(v[q].y, w[q], ay[q]);
            }
        }
        __syncwarp();
    }

    float2 bb = ((const float2*)b)[lane];
    float h0 = ((ax[0] + ax[1]) + (ax[2] + ax[3])) + ((ax[4] + ax[5]) + (ax[6] + ax[7])) + bb.x;
    float h1 = ((ay[0] + ay[1]) + (ay[2] + ay[3])) + ((ay[4] + ay[5]) + (ay[6] + ay[7])) + bb.y;

    float s = h0 + h1;
    #pragma unroll
    for (int o = 16; o > 0; o >>= 1) s += __shfl_xor_sync(0xffffffffu, s, o);
    float mu = s * (1.0f / 64.0f);
    float d0 = h0 - mu, d1 = h1 - mu;
    float vs = d0 * d0 + d1 * d1;
    #pragma unroll
    for (int o = 16; o > 0; o >>= 1) vs += __shfl_xor_sync(0xffffffffu, vs, o);
    float inv = rsqrtf(vs * (1.0f / 64.0f) + 1e-5f);

    float2 gg = ((const float2*)gamma)[lane];
    float2 be = ((const float2*)beta)[lane];
    float y0 = fmaf(d0 * inv, gg.x, be.x);
    float y1 = fmaf(d1 * inv, gg.y, be.y);
    y0 = __fdividef(y0, 1.0f + __expf(-y0));
    y1 = __fdividef(y1, 1.0f + __expf(-y1));

    float2 xv = ((const float2*)(x + (size_t)node * CH))[lane];
    ((float2*)(out + (size_t)node * CH))[lane] = make_float2(y0 + xv.x, y1 + xv.y);
}

// ---------------------------------------------------------------------------
extern "C" void kernel_launch(void* const* d_in, const int* in_sizes, int n_in,
                              void* d_out, int out_size) {
    const float* x     = (const float*)d_in[0];
    const void*  ei    = d_in[1];
    const float* ea    = (const float*)d_in[2];
    const float* W     = (const float*)d_in[3];
    const float* b     = (const float*)d_in[4];
    const float* W1    = (const float*)d_in[5];
    const float* b1    = (const float*)d_in[6];
    const float* W2    = (const float*)d_in[7];
    const float* b2    = (const float*)d_in[8];
    const float* gamma = (const float*)d_in[9];
    const float* beta  = (const float*)d_in[10];
    float* out = (float*)d_out;

    static cudaStream_t s_side = nullptr;
    static cudaEvent_t  s_evFork = nullptr, s_evJoin = nullptr;
    if (!s_side) {
        cudaStreamCreateWithFlags(&s_side, cudaStreamNonBlocking);
        cudaEventCreateWithFlags(&s_evFork, cudaEventDisableTiming);
        cudaEventCreateWithFlags(&s_evJoin, cudaEventDisableTiming);
    }

    // (1) init + detect
    k_detect_init<<<(N_NODES + 255) / 256, 256>>>((const long long*)ei);
    cudaEventRecord(s_evFork, 0);

    // main chain
    k_edge<<<(N_EDGES / 2 + 255) / 256, 256>>>(ea, ei, W1, b1, W2, b2);
    k_scan<<<NB_SCAN, 1024>>>();
    k_place<<<(N_EDGES / 2 + 255) / 256, 256>>>(ei);

    // xw on side stream; overlaps edge/scan/place via fork event
    cudaStreamWaitEvent(s_side, s_evFork, 0);
    k_xw<<<(N_NODES + 63) / 64, 256, 0, s_side>>>(x, W);
    cudaEventRecord(s_evJoin, s_side);

    // join: gather needs g_xw + CSR
    cudaStreamWaitEvent(0, s_evJoin, 0);
    k_gather_ln<<<(N_NODES + 7) / 8, 256>>>(x, b, gamma, beta, out);
}

// round 15
// speedup vs baseline: 1.0462x; 1.0462x over previous
#include <cuda_runtime.h>
#include <cstdint>

#define N_NODES 100000
#define N_EDGES 1600000
#define CH 64
#define EDIM 16
#define HID 32
#define NB_SCAN ((N_NODES + 1023) / 1024)   // 98

// Scratch (static device globals — allocation-free)
__device__ float g_xw[N_NODES * CH];              // x @ W
__device__ float g_alpha[N_EDGES];                // edge gate
__device__ float g_deg[N_NODES];                  // degree -> dis
__device__ int   g_cnt[N_NODES];
__device__ int   g_rowptr[N_NODES];
__device__ int   g_wptr[N_NODES];
__device__ unsigned long long g_epack[N_EDGES];   // (norm<<32 | row_byteoff)
__device__ int   g_is64;
__device__ int   g_base;                          // ticket counter for block offsets

// ---------------------------------------------------------------------------
// dtype detection (one warp, parallel) + zero deg/cnt + zero ticket
// ---------------------------------------------------------------------------
__global__ void k_detect_init(const long long* __restrict__ ei64) {
    int i = blockIdx.x * blockDim.x + threadIdx.x;
    if (blockIdx.x == 0 && threadIdx.x < 32) {
        long long v0 = ei64[threadIdx.x];
        long long v1 = ei64[threadIdx.x + 32];
        int ok = (v0 >= 0 && v0 < N_NODES && v1 >= 0 && v1 < N_NODES) ? 1 : 0;
        unsigned m = __ballot_sync(0xffffffffu, ok);
        if (threadIdx.x == 0) { g_is64 = (m == 0xffffffffu); g_base = 0; }
    }
    if (i < N_NODES) { g_deg[i] = 0.0f; g_cnt[i] = 0; }
}

// ---------------------------------------------------------------------------
// 1) xw = x @ W — smem-tiled GEMM.  64 nodes/block, 4x4 register tile/thread.
// ---------------------------------------------------------------------------
__global__ void k_xw(const float* __restrict__ x, const float* __restrict__ W) {
    __shared__ float Ws[CH * CH];        // [k][c]  16KB
    __shared__ float xs[CH][CH];         // [k][n]  16KB (transposed tile)

    const int tid = threadIdx.x;
    const int nodeBase = blockIdx.x * 64;

    for (int i = tid; i < CH * CH / 4; i += 256)
        ((float4*)Ws)[i] = ((const float4*)W)[i];

    {
        int n  = tid >> 2;               // 0..63
        int k4 = (tid & 3) * 4;          // 0,4,8,12 (+16 per iter)
        int gn = nodeBase + n;
        #pragma unroll
        for (int it = 0; it < 4; ++it) {
            int k = k4 + it * 16;
            float4 v = make_float4(0.f, 0.f, 0.f, 0.f);
            if (gn < N_NODES) v = *(const float4*)(x + (size_t)gn * CH + k);
            xs[k + 0][n] = v.x; xs[k + 1][n] = v.y;
            xs[k + 2][n] = v.z; xs[k + 3][n] = v.w;
        }
    }
    __syncthreads();

    const int c0 = (tid & 15) * 4;
    const int n0 = (tid >> 4) * 4;
    float acc[4][4];
    #pragma unroll
    for (int i = 0; i < 4; ++i)
        #pragma unroll
        for (int j = 0; j < 4; ++j) acc[i][j] = 0.f;

    #pragma unroll 4
    for (int k = 0; k < CH; ++k) {
        float4 a = *(const float4*)&xs[k][n0];
        float4 w = *(const float4*)&Ws[k * CH + c0];
        acc[0][0] = fmaf(a.x, w.x, acc[0][0]); acc[0][1] = fmaf(a.x, w.y, acc[0][1]);
        acc[0][2] = fmaf(a.x, w.z, acc[0][2]); acc[0][3] = fmaf(a.x, w.w, acc[0][3]);
        acc[1][0] = fmaf(a.y, w.x, acc[1][0]); acc[1][1] = fmaf(a.y, w.y, acc[1][1]);
        acc[1][2] = fmaf(a.y, w.z, acc[1][2]); acc[1][3] = fmaf(a.y, w.w, acc[1][3]);
        acc[2][0] = fmaf(a.z, w.x, acc[2][0]); acc[2][1] = fmaf(a.z, w.y, acc[2][1]);
        acc[2][2] = fmaf(a.z, w.z, acc[2][2]); acc[2][3] = fmaf(a.z, w.w, acc[2][3]);
        acc[3][0] = fmaf(a.w, w.x, acc[3][0]); acc[3][1] = fmaf(a.w, w.y, acc[3][1]);
        acc[3][2] = fmaf(a.w, w.z, acc[3][2]); acc[3][3] = fmaf(a.w, w.w, acc[3][3]);
    }

    #pragma unroll
    for (int i = 0; i < 4; ++i) {
        int gn = nodeBase + n0 + i;
        if (gn < N_NODES)
            *(float4*)(g_xw + (size_t)gn * CH + c0) =
                make_float4(acc[i][0], acc[i][1], acc[i][2], acc[i][3]);
    }
}

// ---------------------------------------------------------------------------
// 2) edge MLP gate + degree + count.  2 edges/thread, W1t in smem (LDS.128).
//    (R13-proven: REDG atomics, no ticket)
// ---------------------------------------------------------------------------
__global__ void k_edge(const float* __restrict__ ea,
                       const void* __restrict__ ei,
                       const float* __restrict__ W1, const float* __restrict__ b1,
                       const float* __restrict__ W2, const float* __restrict__ b2) {
    __shared__ __align__(16) float sW1t[HID * EDIM];   // [j][k] transposed
    __shared__ float sb1[HID];
    __shared__ float sW2[HID];
    __shared__ float sb2;
    for (int i = threadIdx.x; i < HID * EDIM; i += blockDim.x) {
        int j = i >> 4, k = i & 15;
        sW1t[i] = W1[k * HID + j];
    }
    if (threadIdx.x < HID) { sb1[threadIdx.x] = b1[threadIdx.x]; sW2[threadIdx.x] = W2[threadIdx.x]; }
    if (threadIdx.x == 0) sb2 = b2[0];
    __syncthreads();

    int t  = blockIdx.x * blockDim.x + threadIdx.x;
    int e0 = 2 * t;
    if (e0 >= N_EDGES) return;      // N_EDGES even -> e0+1 also valid

    float4 A0[4], A1[4];
    {
        const float4* p0 = (const float4*)(ea + (size_t)e0 * EDIM);
        const float4* p1 = (const float4*)(ea + (size_t)(e0 + 1) * EDIM);
        #pragma unroll
        for (int i = 0; i < 4; ++i) { A0[i] = p0[i]; A1[i] = p1[i]; }
    }

    const float4* Wt = (const float4*)sW1t;
    float acc0 = sb2, acc1 = sb2;
    #pragma unroll
    for (int j = 0; j < HID; ++j) {
        float bj = sb1[j];
        float h0 = bj, h1 = bj;
        #pragma unroll
        for (int q = 0; q < 4; ++q) {
            float4 w = Wt[j * 4 + q];
            float4 a = A0[q], c = A1[q];
            h0 = fmaf(a.x, w.x, h0);  h1 = fmaf(c.x, w.x, h1);
            h0 = fmaf(a.y, w.y, h0);  h1 = fmaf(c.y, w.y, h1);
            h0 = fmaf(a.z, w.z, h0);  h1 = fmaf(c.z, w.z, h1);
            h0 = fmaf(a.w, w.w, h0);  h1 = fmaf(c.w, w.w, h1);
        }
        float w2 = sW2[j];
        float s0 = __fdividef(h0, 1.0f + __expf(-h0));   // silu
        float s1 = __fdividef(h1, 1.0f + __expf(-h1));
        acc0 = fmaf(s0, w2, acc0);
        acc1 = fmaf(s1, w2, acc1);
    }
    float alpha0 = __fdividef(1.0f, 1.0f + __expf(-acc0)); // sigmoid
    float alpha1 = __fdividef(1.0f, 1.0f + __expf(-acc1));
    ((float2*)g_alpha)[t] = make_float2(alpha0, alpha1);

    int col0, col1;
    if (g_is64) {
        col0 = (int)((const long long*)ei)[(size_t)N_EDGES + e0];
        col1 = (int)((const long long*)ei)[(size_t)N_EDGES + e0 + 1];
    } else {
        col0 = ((const int*)ei)[(size_t)N_EDGES + e0];
        col1 = ((const int*)ei)[(size_t)N_EDGES + e0 + 1];
    }
    atomicAdd(&g_deg[col0], alpha0);
    atomicAdd(&g_cnt[col0], 1);
    atomicAdd(&g_deg[col1], alpha1);
    atomicAdd(&g_cnt[col1], 1);
}

// ---------------------------------------------------------------------------
// 3) single-pass scan: block-local inclusive scan + atomic ticket offsets,
//    rowptr/wptr + dis = rsqrt(deg) inline.
// ---------------------------------------------------------------------------
__global__ void k_scan() {
    int i = blockIdx.x * 1024 + threadIdx.x;
    int v = (i < N_NODES) ? g_cnt[i] : 0;
    int lane = threadIdx.x & 31, wid = threadIdx.x >> 5;
    int s = v;
    #pragma unroll
    for (int o = 1; o < 32; o <<= 1) {
        int t = __shfl_up_sync(0xffffffffu, s, o);
        if (lane >= o) s += t;
    }
    __shared__ int wsum[32];
    __shared__ int blkoff;
    if (lane == 31) wsum[wid] = s;
    __syncthreads();
    if (wid == 0) {
        int t = wsum[lane];
        #pragma unroll
        for (int o = 1; o < 32; o <<= 1) {
            int u = __shfl_up_sync(0xffffffffu, t, o);
            if (lane >= o) t += u;
        }
        wsum[lane] = t;
        if (lane == 31) blkoff = atomicAdd(&g_base, t);  // t = block total
    }
    __syncthreads();
    if (i < N_NODES) {
        int incl = s + (wid > 0 ? wsum[wid - 1] : 0);
        int excl = incl - v + blkoff;
        g_rowptr[i] = excl;
        g_wptr[i]   = excl;
        float d = g_deg[i];
        g_deg[i] = (d > 0.0f) ? rsqrtf(d) : 0.0f;
    }
}

// ---------------------------------------------------------------------------
// 4) placement: packed (norm, row_byteoffset) into col's CSR slot.
//    row_byteoffset = row * CH * 4 (<< 8) -> gather does zero address math.
// ---------------------------------------------------------------------------
__global__ void k_place(const void* __restrict__ ei) {
    int e = blockIdx.x * blockDim.x + threadIdx.x;
    if (e >= N_EDGES) return;
    int row, col;
    if (g_is64) {
        row = (int)((const long long*)ei)[e];
        col = (int)((const long long*)ei)[(size_t)N_EDGES + e];
    } else {
        row = ((const int*)ei)[e];
        col = ((const int*)ei)[(size_t)N_EDGES + e];
    }
    float norm = g_deg[row] * g_alpha[e] * g_deg[col];
    int pos = atomicAdd(&g_wptr[col], 1);
    unsigned long long v = (unsigned)(row << 8) |        // byte offset into g_xw
                           ((unsigned long long)__float_as_uint(norm) << 32);
    g_epack[pos] = v;
}

// ---------------------------------------------------------------------------
// 5) gather + bias + LayerNorm + SiLU + residual.  One warp per node, MLP=8.
//    epack carries byte offsets -> gather address = base + off (one IADD).
// ---------------------------------------------------------------------------
__global__ void k_gather_ln(const float* __restrict__ x, const float* __restrict__ b,
                            const float* __restrict__ gamma, const float* __restrict__ beta,
                            float* __restrict__ out) {
    __shared__ unsigned long long stage[8][40];
    int wip  = threadIdx.x >> 5;
    int lane = threadIdx.x & 31;
    int node = (blockIdx.x * blockDim.x + threadIdx.x) >> 5;
    if (node >= N_NODES) return;

    if (lane < 8) stage[wip][32 + lane] = 0ull;

    int start = g_rowptr[node];
    int cnt   = g_cnt[node];

    // per-thread base: &g_xw[0] + lane's channel-pair byte offset
    const char* xwb = (const char*)g_xw + lane * 8;

    float ax[8], ay[8];
    #pragma unroll
    for (int i = 0; i < 8; ++i) { ax[i] = 0.f; ay[i] = 0.f; }

    for (int base = 0; base < cnt; base += 32) {
        int m = cnt - base; if (m > 32) m = 32;
        unsigned long long p = 0ull;
        if (lane < m) p = g_epack[start + base + lane];
        stage[wip][lane] = p;
        __syncwarp();
        int m8 = (m + 7) & ~7;
        #pragma unroll 1
        for (int j = 0; j < m8; j += 8) {
            unsigned off[8]; float w[8];
            #pragma unroll
            for (int q = 0; q < 8; ++q) {
                unsigned long long pq = stage[wip][j + q];
                off[q] = (unsigned)pq;                      // byte offset
                w[q]   = __uint_as_float((unsigned)(pq >> 32));
            }
            float2 v[8];
            #pragma unroll
            for (int q = 0; q < 8; ++q)
                v[q] = *(const float2*)(xwb + off[q]);
            #pragma unroll
            for (int q = 0; q < 8; ++q) {
                ax[q] = fmaf(v[q].x, w[q], ax[q]);
                ay[q] = fmaf(v[q].y, w[q], ay[q]);
            }
        }
        __syncwarp();
    }

    float2 bb = ((const float2*)b)[lane];
    float h0 = ((ax[0] + ax[1]) + (ax[2] + ax[3])) + ((ax[4] + ax[5]) + (ax[6] + ax[7])) + bb.x;
    float h1 = ((ay[0] + ay[1]) + (ay[2] + ay[3])) + ((ay[4] + ay[5]) + (ay[6] + ay[7])) + bb.y;

    float s = h0 + h1;
    #pragma unroll
    for (int o = 16; o > 0; o >>= 1) s += __shfl_xor_sync(0xffffffffu, s, o);
    float mu = s * (1.0f / 64.0f);
    float d0 = h0 - mu, d1 = h1 - mu;
    float vs = d0 * d0 + d1 * d1;
    #pragma unroll
    for (int o = 16; o > 0; o >>= 1) vs += __shfl_xor_sync(0xffffffffu, vs, o);
    float inv = rsqrtf(vs * (1.0f / 64.0f) + 1e-5f);

    float2 gg = ((const float2*)gamma)[lane];
    float2 be = ((const float2*)beta)[lane];
    float y0 = fmaf(d0 * inv, gg.x, be.x);
    float y1 = fmaf(d1 * inv, gg.y, be.y);
    y0 = __fdividef(y0, 1.0f + __expf(-y0));
    y1 = __fdividef(y1, 1.0f + __expf(-y1));

    float2 xv = ((const float2*)(x + (size_t)node * CH))[lane];
    ((float2*)(out + (size_t)node * CH))[lane] = make_float2(y0 + xv.x, y1 + xv.y);
}

// ---------------------------------------------------------------------------
extern "C" void kernel_launch(void* const* d_in, const int* in_sizes, int n_in,
                              void* d_out, int out_size) {
    const float* x     = (const float*)d_in[0];
    const void*  ei    = d_in[1];
    const float* ea    = (const float*)d_in[2];
    const float* W     = (const float*)d_in[3];
    const float* b     = (const float*)d_in[4];
    const float* W1    = (const float*)d_in[5];
    const float* b1    = (const float*)d_in[6];
    const float* W2    = (const float*)d_in[7];
    const float* b2    = (const float*)d_in[8];
    const float* gamma = (const float*)d_in[9];
    const float* beta  = (const float*)d_in[10];
    float* out = (float*)d_out;

    static cudaStream_t s_side = nullptr;
    static cudaEvent_t  s_evFork = nullptr, s_evJoin = nullptr;
    if (!s_side) {
        cudaStreamCreateWithFlags(&s_side, cudaStreamNonBlocking);
        cudaEventCreateWithFlags(&s_evFork, cudaEventDisableTiming);
        cudaEventCreateWithFlags(&s_evJoin, cudaEventDisableTiming);
    }

    // (1) init + detect
    k_detect_init<<<(N_NODES + 255) / 256, 256>>>((const long long*)ei);
    cudaEventRecord(s_evFork, 0);

    // main chain
    k_edge<<<(N_EDGES / 2 + 255) / 256, 256>>>(ea, ei, W1, b1, W2, b2);
    k_scan<<<NB_SCAN, 1024>>>();
    k_place<<<(N_EDGES + 255) / 256, 256>>>(ei);

    // xw on side stream; overlaps edge/scan/place via fork event
    cudaStreamWaitEvent(s_side, s_evFork, 0);
    k_xw<<<(N_NODES + 63) / 64, 256, 0, s_side>>>(x, W);
    cudaEventRecord(s_evJoin, s_side);

    // join: gather needs g_xw + CSR
    cudaStreamWaitEvent(0, s_evJoin, 0);
    k_gather_ln<<<(N_NODES + 7) / 8, 256>>>(x, b, gamma, beta, out);
}